// round 2
// baseline (speedup 1.0000x reference)
#include <cuda_runtime.h>
#include <math.h>

#define MAXN 50000
#define MAXE 800000
#define D 128
#define NLAYERS 9
#define NGRAPHS 256
#define ONE_PLUS_EPS 1.00001f

// ---------------- scratch (static device globals; no allocation) ----------------
__device__ float  g_h[MAXN * D];        // node features (in-place updated)
__device__ float  g_aggr[MAXN * D];     // per-layer aggregation
__device__ int    g_rowoff[MAXN + 1];   // CSR row offsets (by dst)
__device__ int    g_cursor[MAXN];       // degree histogram -> scatter cursor
__device__ int    g_srcperm[MAXE];      // src node per CSR slot
__device__ float4 g_ea4[MAXE];          // edge_attr (4 floats) permuted to CSR order
__device__ float  g_pooled[NGRAPHS * D];

// ---------------- CSR build ----------------
__global__ void zero_deg_kernel(int N) {
    int i = blockIdx.x * blockDim.x + threadIdx.x;
    if (i < N) g_cursor[i] = 0;
}

__global__ void hist_kernel(const int* __restrict__ dst, int E) {
    int e = blockIdx.x * blockDim.x + threadIdx.x;
    if (e < E) atomicAdd(&g_cursor[dst[e]], 1);
}

// single-block exclusive scan over degrees -> row offsets; resets cursor to offsets
__global__ void scan_kernel(int N) {
    __shared__ int sums[1024];
    int t = threadIdx.x;
    int chunk = (N + 1023) >> 10;
    int b0 = t * chunk;
    int b1 = min(b0 + chunk, N);
    int s = 0;
    for (int i = b0; i < b1; i++) s += g_cursor[i];
    sums[t] = s;
    __syncthreads();
    for (int off = 1; off < 1024; off <<= 1) {
        int v = (t >= off) ? sums[t - off] : 0;
        __syncthreads();
        sums[t] += v;
        __syncthreads();
    }
    int base = (t == 0) ? 0 : sums[t - 1];
    for (int i = b0; i < b1; i++) {
        int dv = g_cursor[i];
        g_rowoff[i] = base;
        g_cursor[i] = base;
        base += dv;
    }
    if (t == 1023) g_rowoff[N] = sums[1023];
}

__global__ void scatter_kernel(const int* __restrict__ src,
                               const int* __restrict__ dst,
                               const float4* __restrict__ attr4, int E) {
    int e = blockIdx.x * blockDim.x + threadIdx.x;
    if (e >= E) return;
    int d = dst[e];
    int p = atomicAdd(&g_cursor[d], 1);
    g_srcperm[p] = src[e];
    g_ea4[p] = attr4[e];
}

// ---------------- h = x @ Wv ----------------
__global__ void init_h_kernel(const float* __restrict__ x,
                              const float* __restrict__ Wv, int N) {
    __shared__ float xr[13];
    int n = blockIdx.x;
    if (n >= N) return;
    int d = threadIdx.x;  // 128
    if (d < 13) xr[d] = x[(long)n * 13 + d];
    __syncthreads();
    float s = 0.f;
#pragma unroll
    for (int k = 0; k < 13; k++) s = fmaf(xr[k], Wv[k * D + d], s);
    g_h[n * D + d] = s;
}

// ---------------- per-layer aggregation: aggr[n] = sum_{e:dst=n} relu(h[src] + attr@We) ----------------
__global__ __launch_bounds__(256) void aggr_kernel(const float* __restrict__ We, int N) {
    int gw = (blockIdx.x * blockDim.x + threadIdx.x) >> 5;
    int lane = threadIdx.x & 31;
    if (gw >= N) return;

    // each lane owns 4 output dims; preload its 4x4 slice of We into registers
    float wk[4][4];
#pragma unroll
    for (int k = 0; k < 4; k++) {
        float4 t = *(const float4*)&We[k * D + lane * 4];
        wk[k][0] = t.x; wk[k][1] = t.y; wk[k][2] = t.z; wk[k][3] = t.w;
    }

    float4 acc = make_float4(0.f, 0.f, 0.f, 0.f);
    int e0 = g_rowoff[gw];
    int e1 = g_rowoff[gw + 1];
    for (int e = e0; e < e1; e++) {
        int s = g_srcperm[e];
        float4 a = g_ea4[e];
        float4 hs = *(const float4*)&g_h[s * D + lane * 4];
        float mx = fmaf(a.x, wk[0][0], fmaf(a.y, wk[1][0], fmaf(a.z, wk[2][0], fmaf(a.w, wk[3][0], hs.x))));
        float my = fmaf(a.x, wk[0][1], fmaf(a.y, wk[1][1], fmaf(a.z, wk[2][1], fmaf(a.w, wk[3][1], hs.y))));
        float mz = fmaf(a.x, wk[0][2], fmaf(a.y, wk[1][2], fmaf(a.z, wk[2][2], fmaf(a.w, wk[3][2], hs.z))));
        float mw = fmaf(a.x, wk[0][3], fmaf(a.y, wk[1][3], fmaf(a.z, wk[2][3], fmaf(a.w, wk[3][3], hs.w))));
        acc.x += fmaxf(mx, 0.f);
        acc.y += fmaxf(my, 0.f);
        acc.z += fmaxf(mz, 0.f);
        acc.w += fmaxf(mw, 0.f);
    }
    *(float4*)&g_aggr[gw * D + lane * 4] = acc;
}

// ---------------- node update: h = relu(((1+eps)h + aggr) @ W + b) + h ----------------
// 128x128 output tile per block, 256 threads, 8x8 micro-tile, in-place.
__global__ __launch_bounds__(256) void node_update_kernel(const float* __restrict__ W,
                                                          const float* __restrict__ bias,
                                                          int N) {
    __shared__ float As[16][132];  // [k][row], padded
    __shared__ float Bs[16][128];  // [k][col]
    int tid = threadIdx.x;
    int tx = tid & 15;
    int ty = tid >> 4;
    int row0 = blockIdx.x * 128;

    float acc[8][8];
#pragma unroll
    for (int i = 0; i < 8; i++)
#pragma unroll
        for (int j = 0; j < 8; j++) acc[i][j] = 0.f;

    int lr = tid >> 2;         // 0..63 (A-load row)
    int lk4 = (tid & 3) * 4;   // 0,4,8,12 (A-load k offset)
    int wc = tid & 31;         // B-load col4
    int wk = tid >> 5;         // B-load k row (x2)

    for (int kk = 0; kk < D; kk += 16) {
        // load A tile = (1+eps)*h + aggr, transposed into As[k][r]
#pragma unroll
        for (int half = 0; half < 2; half++) {
            int r = lr + half * 64;
            int row = row0 + r;
            float4 hv = make_float4(0.f, 0.f, 0.f, 0.f);
            float4 av = make_float4(0.f, 0.f, 0.f, 0.f);
            if (row < N) {
                hv = *(const float4*)&g_h[row * D + kk + lk4];
                av = *(const float4*)&g_aggr[row * D + kk + lk4];
            }
            As[lk4 + 0][r] = fmaf(ONE_PLUS_EPS, hv.x, av.x);
            As[lk4 + 1][r] = fmaf(ONE_PLUS_EPS, hv.y, av.y);
            As[lk4 + 2][r] = fmaf(ONE_PLUS_EPS, hv.z, av.z);
            As[lk4 + 3][r] = fmaf(ONE_PLUS_EPS, hv.w, av.w);
        }
        // load B tile = W[kk..kk+16][:]
#pragma unroll
        for (int half = 0; half < 2; half++) {
            int k = wk + half * 8;
            float4 wv = *(const float4*)&W[(kk + k) * D + wc * 4];
            *(float4*)&Bs[k][wc * 4] = wv;
        }
        __syncthreads();
#pragma unroll
        for (int k = 0; k < 16; k++) {
            float a[8], b[8];
            *(float4*)&a[0] = *(const float4*)&As[k][ty * 8];
            *(float4*)&a[4] = *(const float4*)&As[k][ty * 8 + 4];
            *(float4*)&b[0] = *(const float4*)&Bs[k][tx * 8];
            *(float4*)&b[4] = *(const float4*)&Bs[k][tx * 8 + 4];
#pragma unroll
            for (int i = 0; i < 8; i++)
#pragma unroll
                for (int j = 0; j < 8; j++) acc[i][j] = fmaf(a[i], b[j], acc[i][j]);
        }
        __syncthreads();
    }

    // epilogue: relu(acc + b) + h, in place
    float bb[8];
    *(float4*)&bb[0] = *(const float4*)&bias[tx * 8];
    *(float4*)&bb[4] = *(const float4*)&bias[tx * 8 + 4];
#pragma unroll
    for (int i = 0; i < 8; i++) {
        int row = row0 + ty * 8 + i;
        if (row >= N) break;
        float4 h0 = *(const float4*)&g_h[row * D + tx * 8];
        float4 h1 = *(const float4*)&g_h[row * D + tx * 8 + 4];
        float o0 = fmaxf(acc[i][0] + bb[0], 0.f) + h0.x;
        float o1 = fmaxf(acc[i][1] + bb[1], 0.f) + h0.y;
        float o2 = fmaxf(acc[i][2] + bb[2], 0.f) + h0.z;
        float o3 = fmaxf(acc[i][3] + bb[3], 0.f) + h0.w;
        float o4 = fmaxf(acc[i][4] + bb[4], 0.f) + h1.x;
        float o5 = fmaxf(acc[i][5] + bb[5], 0.f) + h1.y;
        float o6 = fmaxf(acc[i][6] + bb[6], 0.f) + h1.z;
        float o7 = fmaxf(acc[i][7] + bb[7], 0.f) + h1.w;
        *(float4*)&g_h[row * D + tx * 8]     = make_float4(o0, o1, o2, o3);
        *(float4*)&g_h[row * D + tx * 8 + 4] = make_float4(o4, o5, o6, o7);
    }
}

// ---------------- mean pool per graph (batch is sorted int32) ----------------
__global__ void pool_kernel(const int* __restrict__ batch, int N) {
    int g = blockIdx.x;
    int d = threadIdx.x;  // 128
    // lower bound for g and g+1
    int lo = 0, hi = N;
    while (lo < hi) { int m = (lo + hi) >> 1; if (batch[m] < g) lo = m + 1; else hi = m; }
    int start = lo;
    lo = start; hi = N;
    while (lo < hi) { int m = (lo + hi) >> 1; if (batch[m] < g + 1) lo = m + 1; else hi = m; }
    int end = lo;
    float s = 0.f;
    for (int n = start; n < end; n++) s += g_h[n * D + d];
    float cnt = (float)(end - start);
    g_pooled[g * D + d] = s / fmaxf(cnt, 1.0f);
}

// ---------------- out = gelu(pooled @ Wh1 + bh1) @ Wh2 + bh2 ----------------
__global__ __launch_bounds__(512) void mlp_kernel(const float* __restrict__ Wh1,
                                                  const float* __restrict__ bh1,
                                                  const float* __restrict__ Wh2,
                                                  const float* __restrict__ bh2,
                                                  float* __restrict__ out) {
    int g = blockIdx.x;
    int j = threadIdx.x;  // 512
    __shared__ float p[D];
    __shared__ float red[512];
    if (j < D) p[j] = g_pooled[g * D + j];
    __syncthreads();
    float s = bh1[j];
#pragma unroll 8
    for (int k = 0; k < D; k++) s = fmaf(p[k], Wh1[k * 512 + j], s);
    // exact gelu
    float ge = 0.5f * s * (1.0f + erff(s * 0.70710678118654752f));
    red[j] = ge * Wh2[j];
    __syncthreads();
    for (int off = 256; off > 0; off >>= 1) {
        if (j < off) red[j] += red[j + off];
        __syncthreads();
    }
    if (j == 0) out[g] = red[0] + bh2[0];
}

// ---------------- launcher ----------------
extern "C" void kernel_launch(void* const* d_in, const int* in_sizes, int n_in,
                              void* d_out, int out_size) {
    const float* x     = (const float*)d_in[0];
    const int*   ei    = (const int*)d_in[1];     // int32 (JAX canonicalizes int64->int32)
    const float* eattr = (const float*)d_in[2];
    const int*   batch = (const int*)d_in[3];
    const float* Wv    = (const float*)d_in[4];
    const float* We    = (const float*)d_in[5];
    const float* convw = (const float*)d_in[6];
    const float* convb = (const float*)d_in[7];
    const float* Wh1   = (const float*)d_in[8];
    const float* bh1   = (const float*)d_in[9];
    const float* Wh2   = (const float*)d_in[10];
    const float* bh2   = (const float*)d_in[11];
    float* out = (float*)d_out;

    int N = in_sizes[0] / 13;
    int E = in_sizes[2] / 4;
    int G = out_size;  // 256

    const int* src = ei;
    const int* dst = ei + E;

    // build CSR (by dst) + permuted edge_attr
    zero_deg_kernel<<<(N + 255) / 256, 256>>>(N);
    hist_kernel<<<(E + 255) / 256, 256>>>(dst, E);
    scan_kernel<<<1, 1024>>>(N);
    scatter_kernel<<<(E + 255) / 256, 256>>>(src, dst, (const float4*)eattr, E);

    // h = x @ Wv
    init_h_kernel<<<N, 128>>>(x, Wv, N);

    for (int l = 0; l < NLAYERS; l++) {
        aggr_kernel<<<(N * 32 + 255) / 256, 256>>>(We, N);
        node_update_kernel<<<(N + 127) / 128, 256>>>(convw + (long)l * D * D, convb + (long)l * D, N);
    }

    pool_kernel<<<G, 128>>>(batch, N);
    mlp_kernel<<<G, 512>>>(Wh1, bh1, Wh2, bh2, out);
}